// round 1
// baseline (speedup 1.0000x reference)
#include <cuda_runtime.h>
#include <cstdint>
#include <cstddef>

// Problem dims (fixed by the reference)
#define BDIM 16384
#define ADIM 512
#define MDIM 1024
#define INV_TAU 10.0f

constexpr int BM = 128, BN = 128, BK = 32;
constexpr int PADLD = 36;                              // smem row stride in floats (4*lrow+lcol banks -> conflict-free)
constexpr int SMEM_FLOATS = 2 * BM * PADLD + 2 * BN * PADLD;   // double-buffered A + B tiles
constexpr int SMEM_BYTES = SMEM_FLOATS * 4;            // 73728 B

// Scratch (allocation-free rule: __device__ globals)
__device__ float g_drive[(size_t)BDIM * ADIM];
__device__ float g_sigma[(size_t)BDIM * ADIM];

__device__ __forceinline__ uint32_t cvt_tf32(float v) {
    uint32_t r;
    asm("cvt.rna.tf32.f32 %0, %1;" : "=r"(r) : "f"(v));
    return r;
}

__device__ __forceinline__ void split_tf32(float v, uint32_t& hi, uint32_t& lo) {
    hi = cvt_tf32(v);
    lo = cvt_tf32(v - __uint_as_float(hi));
}

__device__ __forceinline__ void mma_tf32(float c[4], const uint32_t a[4], const uint32_t b[2]) {
    asm volatile(
        "mma.sync.aligned.m16n8k8.row.col.f32.tf32.tf32.f32 "
        "{%0,%1,%2,%3}, {%4,%5,%6,%7}, {%8,%9}, {%0,%1,%2,%3};\n"
        : "+f"(c[0]), "+f"(c[1]), "+f"(c[2]), "+f"(c[3])
        : "r"(a[0]), "r"(a[1]), "r"(a[2]), "r"(a[3]), "r"(b[0]), "r"(b[1]));
}

__device__ __forceinline__ void cp_async16(void* sdst, const void* gsrc) {
    uint32_t s = (uint32_t)__cvta_generic_to_shared(sdst);
    asm volatile("cp.async.cg.shared.global [%0], [%1], 16;\n" ::"r"(s), "l"(gsrc));
}

// C[16384 x 512] = Am[16384 x KDIM] @ Bm[512 x KDIM]^T, tf32x3 (fp32-accurate)
// DRIVE:  outA = C + bias (raw drive), outB = tanh(drive)      (aux = bias[512])
// !DRIVE: outA = tanh(aux + C * INV_TAU)                       (aux = drive[16384x512])
template <int KDIM, bool DRIVE>
__global__ void __launch_bounds__(256, 1)
fused_gemm(const float* __restrict__ Am, const float* __restrict__ Bm,
           const float* __restrict__ aux, float* __restrict__ outA,
           float* __restrict__ outB) {
    extern __shared__ float smem[];
    float* As = smem;                       // [2][BM][PADLD]
    float* Bs = smem + 2 * BM * PADLD;      // [2][BN][PADLD]

    const int tid  = threadIdx.x;
    const int lane = tid & 31;
    const int wid  = tid >> 5;
    const int wm   = wid & 3;     // warp row 0..3  (32 rows each)
    const int wn   = wid >> 2;    // warp col 0..1  (64 cols each)
    const int lrow = lane >> 2;   // 0..7
    const int lcol = lane & 3;    // 0..3

    const int rowBase = blockIdx.y * BM;
    const int colBase = blockIdx.x * BN;

    float acc[2][8][4];
#pragma unroll
    for (int mi = 0; mi < 2; mi++)
#pragma unroll
        for (int ni = 0; ni < 8; ni++)
#pragma unroll
            for (int q = 0; q < 4; q++) acc[mi][ni][q] = 0.f;

    const int ldr = tid >> 3;        // 0..31
    const int ldc = (tid & 7) * 4;   // 0..28 step 4

    auto issue_tile = [&](int kt, int buf) {
        const float* Ag = Am + (size_t)rowBase * KDIM + (size_t)kt * BK;
        const float* Bg = Bm + (size_t)colBase * KDIM + (size_t)kt * BK;
#pragma unroll
        for (int p = 0; p < 4; p++) {
            int r = p * 32 + ldr;
            cp_async16(&As[buf * BM * PADLD + r * PADLD + ldc], Ag + (size_t)r * KDIM + ldc);
            cp_async16(&Bs[buf * BN * PADLD + r * PADLD + ldc], Bg + (size_t)r * KDIM + ldc);
        }
        asm volatile("cp.async.commit_group;\n");
    };

    constexpr int KT = KDIM / BK;
    issue_tile(0, 0);

    for (int kt = 0; kt < KT; ++kt) {
        const int buf = kt & 1;
        if (kt + 1 < KT) {
            issue_tile(kt + 1, buf ^ 1);
            asm volatile("cp.async.wait_group 1;\n");
        } else {
            asm volatile("cp.async.wait_group 0;\n");
        }
        __syncthreads();

        const float* Ab = &As[buf * BM * PADLD];
        const float* Bb = &Bs[buf * BN * PADLD];

#pragma unroll
        for (int k8 = 0; k8 < BK / 8; k8++) {
            uint32_t Ahi[2][4], Alo[2][4];
#pragma unroll
            for (int mi = 0; mi < 2; mi++) {
                const int r0 = wm * 32 + mi * 16 + lrow;
#pragma unroll
                for (int q = 0; q < 4; q++) {
                    const int rr = r0 + ((q & 1) ? 8 : 0);
                    const int cc = k8 * 8 + lcol + ((q & 2) ? 4 : 0);
                    split_tf32(Ab[rr * PADLD + cc], Ahi[mi][q], Alo[mi][q]);
                }
            }
            uint32_t Bhi[8][2], Blo[8][2];
#pragma unroll
            for (int ni = 0; ni < 8; ni++) {
                const int n0 = wn * 64 + ni * 8 + lrow;
                split_tf32(Bb[n0 * PADLD + k8 * 8 + lcol],     Bhi[ni][0], Blo[ni][0]);
                split_tf32(Bb[n0 * PADLD + k8 * 8 + lcol + 4], Bhi[ni][1], Blo[ni][1]);
            }
#pragma unroll
            for (int mi = 0; mi < 2; mi++)
#pragma unroll
                for (int ni = 0; ni < 8; ni++) {
                    mma_tf32(acc[mi][ni], Alo[mi], Bhi[ni]);  // lo*hi
                    mma_tf32(acc[mi][ni], Ahi[mi], Blo[ni]);  // hi*lo
                    mma_tf32(acc[mi][ni], Ahi[mi], Bhi[ni]);  // hi*hi
                }
        }
        __syncthreads();
    }

    // Epilogue
#pragma unroll
    for (int mi = 0; mi < 2; mi++) {
#pragma unroll
        for (int ni = 0; ni < 8; ni++) {
            const int gr = rowBase + wm * 32 + mi * 16 + lrow;
            const int gc = colBase + wn * 64 + ni * 8 + lcol * 2;
            const size_t i0 = (size_t)gr * ADIM + gc;
            const size_t i1 = (size_t)(gr + 8) * ADIM + gc;
            if (DRIVE) {
                const float b0 = aux[gc], b1 = aux[gc + 1];
                const float d0 = acc[mi][ni][0] + b0;
                const float d1 = acc[mi][ni][1] + b1;
                const float d2 = acc[mi][ni][2] + b0;
                const float d3 = acc[mi][ni][3] + b1;
                *(float2*)(outA + i0) = make_float2(d0, d1);
                *(float2*)(outA + i1) = make_float2(d2, d3);
                *(float2*)(outB + i0) = make_float2(tanhf(d0), tanhf(d1));
                *(float2*)(outB + i1) = make_float2(tanhf(d2), tanhf(d3));
            } else {
                const float2 dv0 = *(const float2*)(aux + i0);
                const float2 dv1 = *(const float2*)(aux + i1);
                *(float2*)(outA + i0) =
                    make_float2(tanhf(fmaf(acc[mi][ni][0], INV_TAU, dv0.x)),
                                tanhf(fmaf(acc[mi][ni][1], INV_TAU, dv0.y)));
                *(float2*)(outA + i1) =
                    make_float2(tanhf(fmaf(acc[mi][ni][2], INV_TAU, dv1.x)),
                                tanhf(fmaf(acc[mi][ni][3], INV_TAU, dv1.y)));
            }
        }
    }
}

extern "C" void kernel_launch(void* const* d_in, const int* in_sizes, int n_in,
                              void* d_out, int out_size) {
    (void)in_sizes; (void)n_in; (void)out_size;
    const float* x = (const float*)d_in[0];   // [16384, 1024]
    const float* W = (const float*)d_in[1];   // [512, 1024]
    const float* b = (const float*)d_in[2];   // [512]
    const float* J = (const float*)d_in[3];   // [512, 512]
    float* out = (float*)d_out;               // [16384, 512]

    // Idempotent, capture-safe (non-stream API)
    cudaFuncSetAttribute((const void*)fused_gemm<MDIM, true>,
                         cudaFuncAttributeMaxDynamicSharedMemorySize, SMEM_BYTES);
    cudaFuncSetAttribute((const void*)fused_gemm<ADIM, false>,
                         cudaFuncAttributeMaxDynamicSharedMemorySize, SMEM_BYTES);

    float *drive_p, *sig_p;
    cudaGetSymbolAddress((void**)&drive_p, g_drive);
    cudaGetSymbolAddress((void**)&sig_p, g_sigma);

    dim3 grid(ADIM / BN, BDIM / BM);  // (4, 128)

    // drive = x@W^T + b ; sigma1 = tanh(drive)
    fused_gemm<MDIM, true><<<grid, 256, SMEM_BYTES>>>(x, W, b, drive_p, sig_p);

    // 9 settling GEMM steps; ping-pong so step 10 lands in d_out
    float* bufs[2] = {sig_p, out};
    for (int i = 0; i < 9; i++) {
        fused_gemm<ADIM, false><<<grid, 256, SMEM_BYTES>>>(
            bufs[i & 1], J, drive_p, bufs[(i + 1) & 1], nullptr);
    }
}

// round 2
// speedup vs baseline: 1.8783x; 1.8783x over previous
#include <cuda_runtime.h>
#include <cuda_bf16.h>
#include <cstdint>
#include <cstddef>

#define BDIM 16384
#define ADIM 512
#define MDIM 1024
#define INV_TAU 10.0f

constexpr int BM = 128, BN = 128, BK = 32;
constexpr int PLANE_B = 128 * 64;       // bytes per smem plane (128 rows x 32 bf16 = 64B)
constexpr int STAGE_B = 4 * PLANE_B;    // A_hi, A_lo, B_hi, B_lo
constexpr int SMEM_BYTES = 2 * STAGE_B; // 65536 (double buffered)

// ---- device scratch (allocation-free rule: __device__ globals) ----
__device__ __align__(128) __nv_bfloat16 g_xh[(size_t)BDIM * MDIM];
__device__ __align__(128) __nv_bfloat16 g_xl[(size_t)BDIM * MDIM];
__device__ __align__(128) __nv_bfloat16 g_wh[(size_t)ADIM * MDIM];
__device__ __align__(128) __nv_bfloat16 g_wl[(size_t)ADIM * MDIM];
__device__ __align__(128) __nv_bfloat16 g_jh[(size_t)ADIM * ADIM];
__device__ __align__(128) __nv_bfloat16 g_jl[(size_t)ADIM * ADIM];
__device__ __align__(128) float g_drive[(size_t)BDIM * ADIM];
__device__ __align__(128) __nv_bfloat16 g_sh0[(size_t)BDIM * ADIM];
__device__ __align__(128) __nv_bfloat16 g_sl0[(size_t)BDIM * ADIM];
__device__ __align__(128) __nv_bfloat16 g_sh1[(size_t)BDIM * ADIM];
__device__ __align__(128) __nv_bfloat16 g_sl1[(size_t)BDIM * ADIM];

// ---- helpers ----
__device__ __forceinline__ void cp16(void* sdst, const void* gsrc) {
    uint32_t s = (uint32_t)__cvta_generic_to_shared(sdst);
    asm volatile("cp.async.cg.shared.global [%0], [%1], 16;\n" ::"r"(s), "l"(gsrc));
}

__device__ __forceinline__ void ldsm4(uint32_t* r, const void* p) {
    uint32_t a = (uint32_t)__cvta_generic_to_shared(p);
    asm volatile("ldmatrix.sync.aligned.m8n8.x4.shared.b16 {%0,%1,%2,%3}, [%4];\n"
                 : "=r"(r[0]), "=r"(r[1]), "=r"(r[2]), "=r"(r[3])
                 : "r"(a));
}

__device__ __forceinline__ void mma_bf16(float* c, const uint32_t* a, const uint32_t* b) {
    asm volatile(
        "mma.sync.aligned.m16n8k16.row.col.f32.bf16.bf16.f32 "
        "{%0,%1,%2,%3}, {%4,%5,%6,%7}, {%8,%9}, {%0,%1,%2,%3};\n"
        : "+f"(c[0]), "+f"(c[1]), "+f"(c[2]), "+f"(c[3])
        : "r"(a[0]), "r"(a[1]), "r"(a[2]), "r"(a[3]), "r"(b[0]), "r"(b[1]));
}

// byte offset inside one smem plane for (row, 16B-chunk): conflict-free for
// cp.async STS phases (2 rows x 4 chunks per 128B line) and all LDSM phases
// (8 rows at 64B stride, mats start at rows % 8 == 0).
__device__ __forceinline__ uint32_t swz(int r, int ch) {
    return (uint32_t)(r * 64 + ((ch ^ ((r >> 1) & 3)) << 4));
}

__device__ __forceinline__ void store_split(__nv_bfloat16* hi, __nv_bfloat16* lo,
                                            size_t i, float a, float b) {
    __nv_bfloat16 ha = __float2bfloat16_rn(a);
    __nv_bfloat16 hb = __float2bfloat16_rn(b);
    __nv_bfloat162 h2; h2.x = ha; h2.y = hb;
    __nv_bfloat162 l2;
    l2.x = __float2bfloat16_rn(a - __bfloat162float(ha));
    l2.y = __float2bfloat16_rn(b - __bfloat162float(hb));
    *(__nv_bfloat162*)(hi + i) = h2;
    *(__nv_bfloat162*)(lo + i) = l2;
}

// ---- split fp32 tensor into bf16 hi/lo planes ----
__global__ void split_arr(const float4* __restrict__ src, uint2* __restrict__ hi,
                          uint2* __restrict__ lo, int n4) {
    int i = blockIdx.x * blockDim.x + threadIdx.x;
    if (i >= n4) return;
    float4 v = src[i];
    float f[4] = {v.x, v.y, v.z, v.w};
    uint32_t h[4], l[4];
#pragma unroll
    for (int k = 0; k < 4; k++) {
        __nv_bfloat16 hb = __float2bfloat16_rn(f[k]);
        __nv_bfloat16 lb = __float2bfloat16_rn(f[k] - __bfloat162float(hb));
        h[k] = (uint32_t)__bfloat16_as_ushort(hb);
        l[k] = (uint32_t)__bfloat16_as_ushort(lb);
    }
    uint2 ho, lu;
    ho.x = h[0] | (h[1] << 16); ho.y = h[2] | (h[3] << 16);
    lu.x = l[0] | (l[1] << 16); lu.y = l[2] | (l[3] << 16);
    hi[i] = ho;
    lo[i] = lu;
}

// C[16384 x 512] = A[16384 x KD] @ B[512 x KD]^T via bf16x3 split (near-fp32).
// MODE 0 (drive): d = C + aux(bias); of32 = d; (ohi,olo) = split(tanh(d))
// MODE 1 (mid):   s = tanh(aux + C*INV_TAU); (ohi,olo) = split(s)
// MODE 2 (final): of32 = tanh(aux + C*INV_TAU)
template <int KD, int MODE>
__global__ void __launch_bounds__(256, 1)
settle_gemm(const __nv_bfloat16* __restrict__ Ahi, const __nv_bfloat16* __restrict__ Alo,
            const __nv_bfloat16* __restrict__ Bhi, const __nv_bfloat16* __restrict__ Blo,
            const float* __restrict__ aux,
            __nv_bfloat16* __restrict__ ohi, __nv_bfloat16* __restrict__ olo,
            float* __restrict__ of32) {
    extern __shared__ char sm[];
    const int tid = threadIdx.x, lane = tid & 31, wid = tid >> 5;
    const int wm = wid & 3, wn = wid >> 2;
    const int rowBase = blockIdx.y * BM, colBase = blockIdx.x * BN;

    float acc[2][8][4];
#pragma unroll
    for (int mi = 0; mi < 2; mi++)
#pragma unroll
        for (int ni = 0; ni < 8; ni++)
#pragma unroll
            for (int q = 0; q < 4; q++) acc[mi][ni][q] = 0.f;

    auto issue = [&](int kt, int s) {
        char* st = sm + s * STAGE_B;
#pragma unroll
        for (int j = 0; j < 2; j++) {
            int c = tid + j * 256;
            int r = c >> 2, ch = c & 3;
            uint32_t so = swz(r, ch);
            size_t ga = (size_t)(rowBase + r) * KD + kt * BK + ch * 8;
            size_t gb = (size_t)(colBase + r) * KD + kt * BK + ch * 8;
            cp16(st + 0 * PLANE_B + so, Ahi + ga);
            cp16(st + 1 * PLANE_B + so, Alo + ga);
            cp16(st + 2 * PLANE_B + so, Bhi + gb);
            cp16(st + 3 * PLANE_B + so, Blo + gb);
        }
        asm volatile("cp.async.commit_group;\n");
    };

    constexpr int KT = KD / BK;
    issue(0, 0);

    for (int kt = 0; kt < KT; kt++) {
        const int buf = kt & 1;
        if (kt + 1 < KT) {
            issue(kt + 1, buf ^ 1);
            asm volatile("cp.async.wait_group 1;\n");
        } else {
            asm volatile("cp.async.wait_group 0;\n");
        }
        __syncthreads();
        char* st = sm + buf * STAGE_B;

#pragma unroll
        for (int k16 = 0; k16 < 2; k16++) {
            uint32_t ah[2][4], al[2][4], bb[4][4];
            const int achunk = k16 * 2 + (lane >> 4);
            const int arowl = lane & 15;
#pragma unroll
            for (int mi = 0; mi < 2; mi++) {
                int r = wm * 32 + mi * 16 + arowl;
                uint32_t so = swz(r, achunk);
                ldsm4(ah[mi], st + so);
                ldsm4(al[mi], st + PLANE_B + so);
            }
            const int bchunk = k16 * 2 + ((lane >> 3) & 1);
            const int browl = ((lane >> 4) << 3) + (lane & 7);
#pragma unroll
            for (int g = 0; g < 4; g++) {
                int r = wn * 64 + g * 16 + browl;
                ldsm4(bb[g], st + 2 * PLANE_B + swz(r, bchunk));
            }
#pragma unroll
            for (int ni = 0; ni < 8; ni++) {
                const uint32_t* b = &bb[ni >> 1][(ni & 1) * 2];
                mma_bf16(acc[0][ni], ah[0], b);  // hi*hi
                mma_bf16(acc[1][ni], ah[1], b);
                mma_bf16(acc[0][ni], al[0], b);  // lo*hi
                mma_bf16(acc[1][ni], al[1], b);
            }
#pragma unroll
            for (int g = 0; g < 4; g++) {
                int r = wn * 64 + g * 16 + browl;
                ldsm4(bb[g], st + 3 * PLANE_B + swz(r, bchunk));
            }
#pragma unroll
            for (int ni = 0; ni < 8; ni++) {
                const uint32_t* b = &bb[ni >> 1][(ni & 1) * 2];
                mma_bf16(acc[0][ni], ah[0], b);  // hi*lo
                mma_bf16(acc[1][ni], ah[1], b);
            }
        }
        __syncthreads();
    }

    // ---- epilogue ----
    const int lrow = lane >> 2, lcol = lane & 3;
#pragma unroll
    for (int mi = 0; mi < 2; mi++) {
#pragma unroll
        for (int ni = 0; ni < 8; ni++) {
            const int gr = rowBase + wm * 32 + mi * 16 + lrow;
            const int gc = colBase + wn * 64 + ni * 8 + lcol * 2;
            const size_t i0 = (size_t)gr * ADIM + gc;
            const size_t i1 = i0 + (size_t)8 * ADIM;
            float v0 = acc[mi][ni][0], v1 = acc[mi][ni][1];
            float v2 = acc[mi][ni][2], v3 = acc[mi][ni][3];
            if (MODE == 0) {
                const float b0 = aux[gc], b1 = aux[gc + 1];
                v0 += b0; v1 += b1; v2 += b0; v3 += b1;
                *(float2*)(of32 + i0) = make_float2(v0, v1);
                *(float2*)(of32 + i1) = make_float2(v2, v3);
                store_split(ohi, olo, i0, tanhf(v0), tanhf(v1));
                store_split(ohi, olo, i1, tanhf(v2), tanhf(v3));
            } else {
                const float2 d0 = *(const float2*)(aux + i0);
                const float2 d1 = *(const float2*)(aux + i1);
                v0 = tanhf(fmaf(v0, INV_TAU, d0.x));
                v1 = tanhf(fmaf(v1, INV_TAU, d0.y));
                v2 = tanhf(fmaf(v2, INV_TAU, d1.x));
                v3 = tanhf(fmaf(v3, INV_TAU, d1.y));
                if (MODE == 1) {
                    store_split(ohi, olo, i0, v0, v1);
                    store_split(ohi, olo, i1, v2, v3);
                } else {
                    *(float2*)(of32 + i0) = make_float2(v0, v1);
                    *(float2*)(of32 + i1) = make_float2(v2, v3);
                }
            }
        }
    }
}

extern "C" void kernel_launch(void* const* d_in, const int* in_sizes, int n_in,
                              void* d_out, int out_size) {
    (void)in_sizes; (void)n_in; (void)out_size;
    const float* x = (const float*)d_in[0];  // [16384, 1024]
    const float* W = (const float*)d_in[1];  // [512, 1024]
    const float* b = (const float*)d_in[2];  // [512]
    const float* J = (const float*)d_in[3];  // [512, 512]
    float* out = (float*)d_out;              // [16384, 512]

    cudaFuncSetAttribute((const void*)settle_gemm<MDIM, 0>,
                         cudaFuncAttributeMaxDynamicSharedMemorySize, SMEM_BYTES);
    cudaFuncSetAttribute((const void*)settle_gemm<ADIM, 1>,
                         cudaFuncAttributeMaxDynamicSharedMemorySize, SMEM_BYTES);
    cudaFuncSetAttribute((const void*)settle_gemm<ADIM, 2>,
                         cudaFuncAttributeMaxDynamicSharedMemorySize, SMEM_BYTES);

    __nv_bfloat16 *xh, *xl, *wh, *wl, *jh, *jl, *sh0, *sl0, *sh1, *sl1;
    float* drv;
    cudaGetSymbolAddress((void**)&xh, g_xh);
    cudaGetSymbolAddress((void**)&xl, g_xl);
    cudaGetSymbolAddress((void**)&wh, g_wh);
    cudaGetSymbolAddress((void**)&wl, g_wl);
    cudaGetSymbolAddress((void**)&jh, g_jh);
    cudaGetSymbolAddress((void**)&jl, g_jl);
    cudaGetSymbolAddress((void**)&sh0, g_sh0);
    cudaGetSymbolAddress((void**)&sl0, g_sl0);
    cudaGetSymbolAddress((void**)&sh1, g_sh1);
    cudaGetSymbolAddress((void**)&sl1, g_sl1);
    cudaGetSymbolAddress((void**)&drv, g_drive);

    // split inputs into bf16 hi/lo planes
    {
        int n4 = BDIM * MDIM / 4;
        split_arr<<<(n4 + 255) / 256, 256>>>((const float4*)x, (uint2*)xh, (uint2*)xl, n4);
        n4 = ADIM * MDIM / 4;
        split_arr<<<(n4 + 255) / 256, 256>>>((const float4*)W, (uint2*)wh, (uint2*)wl, n4);
        n4 = ADIM * ADIM / 4;
        split_arr<<<(n4 + 255) / 256, 256>>>((const float4*)J, (uint2*)jh, (uint2*)jl, n4);
    }

    dim3 grid(ADIM / BN, BDIM / BM);  // (4, 128)

    // drive = x@W^T + b ; sigma1 = tanh(drive)
    settle_gemm<MDIM, 0><<<grid, 256, SMEM_BYTES>>>(xh, xl, wh, wl, b, sh0, sl0, drv);

    // sigma2..sigma9 (8 mid steps, ping-pong: odd sigmas in buf0)
    __nv_bfloat16* H[2] = {sh0, sh1};
    __nv_bfloat16* L[2] = {sl0, sl1};
    for (int i = 0; i < 8; i++) {
        settle_gemm<ADIM, 1><<<grid, 256, SMEM_BYTES>>>(
            H[i & 1], L[i & 1], jh, jl, drv, H[(i + 1) & 1], L[(i + 1) & 1], nullptr);
    }
    // sigma10 -> d_out (fp32)
    settle_gemm<ADIM, 2><<<grid, 256, SMEM_BYTES>>>(sh0, sl0, jh, jl, drv, nullptr,
                                                    nullptr, out);
}

// round 7
// speedup vs baseline: 2.2344x; 1.1896x over previous
#include <cuda_runtime.h>
#include <cuda_bf16.h>
#include <cstdint>
#include <cstddef>

#define BDIM 16384
#define ADIM 512
#define MDIM 1024
#define INV_TAU 10.0f

constexpr int BM = 128, BN = 128, BK = 32;
constexpr int PLANE_B = 128 * 64;       // bytes per smem plane (128 rows x 32 bf16 = 64B)
constexpr int STAGE_B = 4 * PLANE_B;    // A_hi, A_lo, B_hi, B_lo
constexpr int SMEM_BYTES = 2 * STAGE_B; // 65536 (double buffered)

// ---- device scratch (allocation-free rule: __device__ globals) ----
__device__ __align__(128) __nv_bfloat16 g_xh[(size_t)BDIM * MDIM];
__device__ __align__(128) __nv_bfloat16 g_xl[(size_t)BDIM * MDIM];
__device__ __align__(128) __nv_bfloat16 g_wh[(size_t)ADIM * MDIM];
__device__ __align__(128) __nv_bfloat16 g_wl[(size_t)ADIM * MDIM];
__device__ __align__(128) __nv_bfloat16 g_jh[(size_t)ADIM * ADIM];
__device__ __align__(128) __nv_bfloat16 g_jl[(size_t)ADIM * ADIM];
__device__ __align__(128) float g_drive[(size_t)BDIM * ADIM];
__device__ __align__(128) __nv_bfloat16 g_sh0[(size_t)BDIM * ADIM];
__device__ __align__(128) __nv_bfloat16 g_sl0[(size_t)BDIM * ADIM];
__device__ __align__(128) __nv_bfloat16 g_sh1[(size_t)BDIM * ADIM];
__device__ __align__(128) __nv_bfloat16 g_sl1[(size_t)BDIM * ADIM];

// ---- helpers ----
__device__ __forceinline__ void cp16(void* sdst, const void* gsrc) {
    uint32_t s = (uint32_t)__cvta_generic_to_shared(sdst);
    asm volatile("cp.async.cg.shared.global [%0], [%1], 16;\n" ::"r"(s), "l"(gsrc));
}

__device__ __forceinline__ void ldsm4(uint32_t* r, const void* p) {
    uint32_t a = (uint32_t)__cvta_generic_to_shared(p);
    asm volatile("ldmatrix.sync.aligned.m8n8.x4.shared.b16 {%0,%1,%2,%3}, [%4];\n"
                 : "=r"(r[0]), "=r"(r[1]), "=r"(r[2]), "=r"(r[3])
                 : "r"(a));
}

__device__ __forceinline__ void mma_bf16(float* c, const uint32_t* a, const uint32_t* b) {
    asm volatile(
        "mma.sync.aligned.m16n8k16.row.col.f32.bf16.bf16.f32 "
        "{%0,%1,%2,%3}, {%4,%5,%6,%7}, {%8,%9}, {%0,%1,%2,%3};\n"
        : "+f"(c[0]), "+f"(c[1]), "+f"(c[2]), "+f"(c[3])
        : "r"(a[0]), "r"(a[1]), "r"(a[2]), "r"(a[3]), "r"(b[0]), "r"(b[1]));
}

// byte offset inside one smem plane for (row, 16B-chunk): conflict-free for
// cp.async STS phases and all LDSM phases.
__device__ __forceinline__ uint32_t swz(int r, int ch) {
    return (uint32_t)(r * 64 + ((ch ^ ((r >> 1) & 3)) << 4));
}

__device__ __forceinline__ void store_split(__nv_bfloat16* hi, __nv_bfloat16* lo,
                                            uint32_t i, float a, float b) {
    __nv_bfloat16 ha = __float2bfloat16_rn(a);
    __nv_bfloat16 hb = __float2bfloat16_rn(b);
    __nv_bfloat162 h2; h2.x = ha; h2.y = hb;
    __nv_bfloat162 l2;
    l2.x = __float2bfloat16_rn(a - __bfloat162float(ha));
    l2.y = __float2bfloat16_rn(b - __bfloat162float(hb));
    *(__nv_bfloat162*)(hi + i) = h2;
    *(__nv_bfloat162*)(lo + i) = l2;
}

// ---- split fp32 tensor into bf16 hi/lo planes ----
__global__ void split_arr(const float4* __restrict__ src, uint2* __restrict__ hi,
                          uint2* __restrict__ lo, int n4) {
    int i = blockIdx.x * blockDim.x + threadIdx.x;
    if (i >= n4) return;
    float4 v = src[i];
    float f[4] = {v.x, v.y, v.z, v.w};
    uint32_t h[4], l[4];
#pragma unroll
    for (int k = 0; k < 4; k++) {
        __nv_bfloat16 hb = __float2bfloat16_rn(f[k]);
        __nv_bfloat16 lb = __float2bfloat16_rn(f[k] - __bfloat162float(hb));
        h[k] = (uint32_t)__bfloat16_as_ushort(hb);
        l[k] = (uint32_t)__bfloat16_as_ushort(lb);
    }
    hi[i] = make_uint2(h[0] | (h[1] << 16), h[2] | (h[3] << 16));
    lo[i] = make_uint2(l[0] | (l[1] << 16), l[2] | (l[3] << 16));
}

// C[16384 x 512] = A[16384 x KD] @ B[512 x KD]^T via bf16x3 split (near-fp32).
// MODE 0 (drive): d = C + aux(bias); of32 = d; (ohi,olo) = split(tanh(d))
// MODE 1 (mid):   s = tanh(aux + C*INV_TAU); (ohi,olo) = split(s)
// MODE 2 (final): of32 = tanh(aux + C*INV_TAU)
template <int KD, int MODE>
__global__ void __launch_bounds__(256, 2)
settle_gemm(const __nv_bfloat16* __restrict__ Ahi, const __nv_bfloat16* __restrict__ Alo,
            const __nv_bfloat16* __restrict__ Bhi, const __nv_bfloat16* __restrict__ Blo,
            const float* __restrict__ aux,
            __nv_bfloat16* __restrict__ ohi, __nv_bfloat16* __restrict__ olo,
            float* __restrict__ of32) {
    extern __shared__ char sm[];
    const int tid = threadIdx.x, lane = tid & 31, wid = tid >> 5;
    const int wm = wid & 3, wn = wid >> 2;
    const int rowBase = blockIdx.y * BM, colBase = blockIdx.x * BN;

    float acc[2][8][4];
#pragma unroll
    for (int mi = 0; mi < 2; mi++)
#pragma unroll
        for (int ni = 0; ni < 8; ni++)
#pragma unroll
            for (int q = 0; q < 4; q++) acc[mi][ni][q] = 0.f;

    // ---- precomputed producer offsets (uint32 element indices) ----
    uint32_t sA[2], gA[2], gB[2];
#pragma unroll
    for (int j = 0; j < 2; j++) {
        int c = tid + j * 256;
        int r = c >> 2, ch = c & 3;
        sA[j] = swz(r, ch);
        gA[j] = (uint32_t)(rowBase + r) * KD + ch * 8;
        gB[j] = (uint32_t)(colBase + r) * KD + ch * 8;
    }

    auto issue = [&](int kt, int s) {
        char* st = sm + s * STAGE_B;
        const uint32_t kof = kt * BK;
#pragma unroll
        for (int j = 0; j < 2; j++) {
            cp16(st + sA[j], Ahi + gA[j] + kof);
            cp16(st + PLANE_B + sA[j], Alo + gA[j] + kof);
            cp16(st + 2 * PLANE_B + sA[j], Bhi + gB[j] + kof);
            cp16(st + 3 * PLANE_B + sA[j], Blo + gB[j] + kof);
        }
        asm volatile("cp.async.commit_group;\n");
    };

    // ---- precomputed ldsm swizzled offsets ----
    const int arowl = lane & 15;
    const int browl = ((lane >> 4) << 3) + (lane & 7);
    uint32_t aOff[2][2], bOff[2][4];   // [k16][mi/g]
#pragma unroll
    for (int k16 = 0; k16 < 2; k16++) {
        const int achunk = k16 * 2 + (lane >> 4);
        const int bchunk = k16 * 2 + ((lane >> 3) & 1);
#pragma unroll
        for (int mi = 0; mi < 2; mi++)
            aOff[k16][mi] = swz(wm * 32 + mi * 16 + arowl, achunk);
#pragma unroll
        for (int g = 0; g < 4; g++)
            bOff[k16][g] = swz(wn * 64 + g * 16 + browl, bchunk);
    }

    constexpr int KT = KD / BK;
    issue(0, 0);

    for (int kt = 0; kt < KT; kt++) {
        const int buf = kt & 1;
        if (kt + 1 < KT) {
            issue(kt + 1, buf ^ 1);
            asm volatile("cp.async.wait_group 1;\n");
        } else {
            asm volatile("cp.async.wait_group 0;\n");
        }
        __syncthreads();
        char* st = sm + buf * STAGE_B;

#pragma unroll
        for (int k16 = 0; k16 < 2; k16++) {
            uint32_t ah[2][4], al[2][4], bb[4][4];
#pragma unroll
            for (int mi = 0; mi < 2; mi++) {
                ldsm4(ah[mi], st + aOff[k16][mi]);
                ldsm4(al[mi], st + PLANE_B + aOff[k16][mi]);
            }
#pragma unroll
            for (int g = 0; g < 4; g++)
                ldsm4(bb[g], st + 2 * PLANE_B + bOff[k16][g]);
#pragma unroll
            for (int ni = 0; ni < 8; ni++) {
                const uint32_t* b = &bb[ni >> 1][(ni & 1) * 2];
                mma_bf16(acc[0][ni], ah[0], b);  // hi*hi
                mma_bf16(acc[1][ni], ah[1], b);
                mma_bf16(acc[0][ni], al[0], b);  // lo*hi
                mma_bf16(acc[1][ni], al[1], b);
            }
#pragma unroll
            for (int g = 0; g < 4; g++)
                ldsm4(bb[g], st + 3 * PLANE_B + bOff[k16][g]);
#pragma unroll
            for (int ni = 0; ni < 8; ni++) {
                const uint32_t* b = &bb[ni >> 1][(ni & 1) * 2];
                mma_bf16(acc[0][ni], ah[0], b);  // hi*lo
                mma_bf16(acc[1][ni], ah[1], b);
            }
        }
        __syncthreads();
    }

    // ---- epilogue ----
    const int lrow = lane >> 2, lcol = lane & 3;
#pragma unroll
    for (int mi = 0; mi < 2; mi++) {
#pragma unroll
        for (int ni = 0; ni < 8; ni++) {
            const int gr = rowBase + wm * 32 + mi * 16 + lrow;
            const int gc = colBase + wn * 64 + ni * 8 + lcol * 2;
            const uint32_t i0 = (uint32_t)gr * ADIM + gc;
            const uint32_t i1 = i0 + 8 * ADIM;
            float v0 = acc[mi][ni][0], v1 = acc[mi][ni][1];
            float v2 = acc[mi][ni][2], v3 = acc[mi][ni][3];
            if (MODE == 0) {
                const float b0 = aux[gc], b1 = aux[gc + 1];
                v0 += b0; v1 += b1; v2 += b0; v3 += b1;
                *(float2*)(of32 + i0) = make_float2(v0, v1);
                *(float2*)(of32 + i1) = make_float2(v2, v3);
                store_split(ohi, olo, i0, tanhf(v0), tanhf(v1));
                store_split(ohi, olo, i1, tanhf(v2), tanhf(v3));
            } else {
                const float2 d0 = *(const float2*)(aux + i0);
                const float2 d1 = *(const float2*)(aux + i1);
                v0 = tanhf(fmaf(v0, INV_TAU, d0.x));
                v1 = tanhf(fmaf(v1, INV_TAU, d0.y));
                v2 = tanhf(fmaf(v2, INV_TAU, d1.x));
                v3 = tanhf(fmaf(v3, INV_TAU, d1.y));
                if (MODE == 1) {
                    store_split(ohi, olo, i0, v0, v1);
                    store_split(ohi, olo, i1, v2, v3);
                } else {
                    *(float2*)(of32 + i0) = make_float2(v0, v1);
                    *(float2*)(of32 + i1) = make_float2(v2, v3);
                }
            }
        }
    }
}

extern "C" void kernel_launch(void* const* d_in, const int* in_sizes, int n_in,
                              void* d_out, int out_size) {
    (void)in_sizes; (void)n_in; (void)out_size;
    const float* x = (const float*)d_in[0];  // [16384, 1024]
    const float* W = (const float*)d_in[1];  // [512, 1024]
    const float* b = (const float*)d_in[2];  // [512]
    const float* J = (const float*)d_in[3];  // [512, 512]
    float* out = (float*)d_out;              // [16384, 512]

    cudaFuncSetAttribute((const void*)settle_gemm<MDIM, 0>,
                         cudaFuncAttributeMaxDynamicSharedMemorySize, SMEM_BYTES);
    cudaFuncSetAttribute((const void*)settle_gemm<ADIM, 1>,
                         cudaFuncAttributeMaxDynamicSharedMemorySize, SMEM_BYTES);
    cudaFuncSetAttribute((const void*)settle_gemm<ADIM, 2>,
                         cudaFuncAttributeMaxDynamicSharedMemorySize, SMEM_BYTES);

    __nv_bfloat16 *xh, *xl, *wh, *wl, *jh, *jl, *sh0, *sl0, *sh1, *sl1;
    float* drv;
    cudaGetSymbolAddress((void**)&xh, g_xh);
    cudaGetSymbolAddress((void**)&xl, g_xl);
    cudaGetSymbolAddress((void**)&wh, g_wh);
    cudaGetSymbolAddress((void**)&wl, g_wl);
    cudaGetSymbolAddress((void**)&jh, g_jh);
    cudaGetSymbolAddress((void**)&jl, g_jl);
    cudaGetSymbolAddress((void**)&sh0, g_sh0);
    cudaGetSymbolAddress((void**)&sl0, g_sl0);
    cudaGetSymbolAddress((void**)&sh1, g_sh1);
    cudaGetSymbolAddress((void**)&sl1, g_sl1);
    cudaGetSymbolAddress((void**)&drv, g_drive);

    // split inputs into bf16 hi/lo planes
    {
        int n4 = BDIM * MDIM / 4;
        split_arr<<<(n4 + 255) / 256, 256>>>((const float4*)x, (uint2*)xh, (uint2*)xl, n4);
        n4 = ADIM * MDIM / 4;
        split_arr<<<(n4 + 255) / 256, 256>>>((const float4*)W, (uint2*)wh, (uint2*)wl, n4);
        n4 = ADIM * ADIM / 4;
        split_arr<<<(n4 + 255) / 256, 256>>>((const float4*)J, (uint2*)jh, (uint2*)jl, n4);
    }

    dim3 grid(ADIM / BN, BDIM / BM);  // (4, 128)

    // drive = x@W^T + b ; sigma1 = tanh(drive)
    settle_gemm<MDIM, 0><<<grid, 256, SMEM_BYTES>>>(xh, xl, wh, wl, b, sh0, sl0, drv);

    // sigma2..sigma9 (8 mid steps, ping-pong)
    __nv_bfloat16* H[2] = {sh0, sh1};
    __nv_bfloat16* L[2] = {sl0, sl1};
    for (int i = 0; i < 8; i++) {
        settle_gemm<ADIM, 1><<<grid, 256, SMEM_BYTES>>>(
            H[i & 1], L[i & 1], jh, jl, drv, H[(i + 1) & 1], L[(i + 1) & 1], nullptr);
    }
    // sigma10 -> d_out (fp32)
    settle_gemm<ADIM, 2><<<grid, 256, SMEM_BYTES>>>(sh0, sl0, jh, jl, drv, nullptr,
                                                    nullptr, out);
}